// round 6
// baseline (speedup 1.0000x reference)
#include <cuda_runtime.h>
#include <cuda_bf16.h>

#define NUM_REL   20000
#define NUM_EDGES 640000
#define DIM       128
#define NUM_HEAD  8
#define DIM_HID   16
#define NUM_BIN   10
#define NEG       0.2f
#define CAP       256   // per-relation shared score cache (cnt ~ Binom(640K,1/20K): mean 32)
#define SCAN_B    79    // ceil(20000/256)

// ---------------- device scratch (static: no allocs allowed) ----------------
__device__ float g_P1[NUM_REL * DIM];
__device__ float g_P2[NUM_REL * DIM];
__device__ float g_M [NUM_REL * DIM];
__device__ float g_attn[NUM_EDGES * NUM_HEAD];  // fallback only (cnt > CAP)
__device__ float g_Wt1[DIM * DIM];
__device__ float g_Wt2[DIM * DIM];
__device__ float g_Wt3[DIM * DIM];
__device__ int   g_cnt[NUM_REL];
__device__ int   g_off[NUM_REL + 1];
__device__ int   g_cur[NUM_REL];
__device__ int   g_sorted[NUM_EDGES];
__device__ int   g_bsum[SCAN_B + 1];

// ---------------- zero counts + weight transpose (merged) ----------------
__global__ void K_pre(const float* __restrict__ attn_w, const float* __restrict__ aggr_w) {
    int id = blockIdx.x * blockDim.x + threadIdx.x;
    if (id < NUM_REL) g_cnt[id] = 0;
    if (id >= 3 * DIM * DIM) return;
    int mtx = id / (DIM * DIM);
    int rem = id % (DIM * DIM);
    int j = rem / DIM, k = rem % DIM;
    if (mtx == 0)       g_Wt1[k * DIM + j] = attn_w[j * (2 * DIM) + k];
    else if (mtx == 1)  g_Wt2[k * DIM + j] = attn_w[j * (2 * DIM) + DIM + k];
    else                g_Wt3[k * DIM + j] = aggr_w[j * DIM + k];
}

__global__ void K_hist(const int* __restrict__ trip) {
    int e = blockIdx.x * blockDim.x + threadIdx.x;
    if (e < NUM_EDGES) atomicAdd(&g_cnt[trip[e * 3]], 1);
}

// ---------------- 3-phase parallel scan ----------------
__global__ void K_scan1() {           // SCAN_B blocks x 256: local exclusive scan
    __shared__ int sh[256];
    int tid = threadIdx.x;
    int i = blockIdx.x * 256 + tid;
    int v = (i < NUM_REL) ? g_cnt[i] : 0;
    sh[tid] = v;
    __syncthreads();
#pragma unroll
    for (int off = 1; off < 256; off <<= 1) {
        int t = (tid >= off) ? sh[tid - off] : 0;
        __syncthreads();
        sh[tid] += t;
        __syncthreads();
    }
    if (i < NUM_REL) g_off[i] = sh[tid] - v;          // local exclusive prefix
    if (tid == 255) g_bsum[blockIdx.x] = sh[255];     // block total
}

__global__ void K_scan2() {           // 1 block x 128: scan the 79 block sums
    __shared__ int sh[128];
    int tid = threadIdx.x;
    int v = (tid < SCAN_B) ? g_bsum[tid] : 0;
    sh[tid] = v;
    __syncthreads();
#pragma unroll
    for (int off = 1; off < 128; off <<= 1) {
        int t = (tid >= off) ? sh[tid - off] : 0;
        __syncthreads();
        sh[tid] += t;
        __syncthreads();
    }
    if (tid < SCAN_B) g_bsum[tid] = sh[tid] - v;      // exclusive base per block
    if (tid == 127) g_off[NUM_REL] = sh[127];         // grand total (= NUM_EDGES)
}

__global__ void K_scan3() {           // SCAN_B blocks x 256: add base, init cursors
    int i = blockIdx.x * 256 + threadIdx.x;
    if (i < NUM_REL) {
        int o = g_off[i] + g_bsum[blockIdx.x];
        g_off[i] = o;
        g_cur[i] = o;
    }
}

__global__ void K_scatter(const int* __restrict__ trip) {
    int e = blockIdx.x * blockDim.x + threadIdx.x;
    if (e < NUM_EDGES) {
        int pos = atomicAdd(&g_cur[trip[e * 3]], 1);
        g_sorted[pos] = e;
    }
}

// ------- 20000x128x128 SGEMM: out[r][j] = sum_k emb[r][k]*Wt[k][j] (+bias) -------
__global__ void __launch_bounds__(256) K_gemm(const float* __restrict__ emb,
                                              const float* __restrict__ bias, int which) {
    const float* __restrict__ Wt = (which == 0) ? g_Wt1 : (which == 1) ? g_Wt2 : g_Wt3;
    float*       __restrict__ op = (which == 0) ? g_P1  : (which == 1) ? g_P2  : g_M;

    __shared__ float embS[32 * 128];
    __shared__ float WtS[32 * 132];   // padded -> conflict-free LDS.128

    int tid = threadIdx.x;
    int rbase = blockIdx.x * 32;

    const float4* eg = (const float4*)(emb + (size_t)rbase * DIM);
#pragma unroll
    for (int i = 0; i < 4; i++)
        ((float4*)embS)[tid + i * 256] = eg[tid + i * 256];

    int jt = tid & 31, j0 = jt * 4;
    int rt = tid >> 5, r0 = rt * 4;

    float acc[4][4];
#pragma unroll
    for (int a = 0; a < 4; a++)
#pragma unroll
        for (int b = 0; b < 4; b++) acc[a][b] = 0.f;

    for (int kc = 0; kc < 4; kc++) {
        __syncthreads();
#pragma unroll
        for (int i = 0; i < 4; i++) {
            int v = tid + i * 256;
            int kl = v >> 5, jq = v & 31;
            *(float4*)&WtS[kl * 132 + jq * 4] = ((const float4*)Wt)[kc * 1024 + v];
        }
        __syncthreads();
#pragma unroll
        for (int kq = 0; kq < 8; kq++) {
            float4 w0 = *(float4*)&WtS[(kq * 4 + 0) * 132 + j0];
            float4 w1 = *(float4*)&WtS[(kq * 4 + 1) * 132 + j0];
            float4 w2 = *(float4*)&WtS[(kq * 4 + 2) * 132 + j0];
            float4 w3 = *(float4*)&WtS[(kq * 4 + 3) * 132 + j0];
            int kk4 = kc * 32 + kq * 4;
#pragma unroll
            for (int a = 0; a < 4; a++) {
                float4 ev = *(float4*)&embS[(r0 + a) * 128 + kk4];   // broadcast LDS.128
                acc[a][0] = fmaf(ev.x, w0.x, acc[a][0]);
                acc[a][1] = fmaf(ev.x, w0.y, acc[a][1]);
                acc[a][2] = fmaf(ev.x, w0.z, acc[a][2]);
                acc[a][3] = fmaf(ev.x, w0.w, acc[a][3]);
                acc[a][0] = fmaf(ev.y, w1.x, acc[a][0]);
                acc[a][1] = fmaf(ev.y, w1.y, acc[a][1]);
                acc[a][2] = fmaf(ev.y, w1.z, acc[a][2]);
                acc[a][3] = fmaf(ev.y, w1.w, acc[a][3]);
                acc[a][0] = fmaf(ev.z, w2.x, acc[a][0]);
                acc[a][1] = fmaf(ev.z, w2.y, acc[a][1]);
                acc[a][2] = fmaf(ev.z, w2.z, acc[a][2]);
                acc[a][3] = fmaf(ev.z, w2.w, acc[a][3]);
                acc[a][0] = fmaf(ev.w, w3.x, acc[a][0]);
                acc[a][1] = fmaf(ev.w, w3.y, acc[a][1]);
                acc[a][2] = fmaf(ev.w, w3.z, acc[a][2]);
                acc[a][3] = fmaf(ev.w, w3.w, acc[a][3]);
            }
        }
    }

    float4 bv = make_float4(0.f, 0.f, 0.f, 0.f);
    if (bias) bv = *(const float4*)(bias + j0);
#pragma unroll
    for (int a = 0; a < 4; a++) {
        float4 o;
        o.x = acc[a][0] + bv.x; o.y = acc[a][1] + bv.y;
        o.z = acc[a][2] + bv.z; o.w = acc[a][3] + bv.w;
        *(float4*)&op[(size_t)(rbase + r0 + a) * DIM + j0] = o;
    }
}

// ---------------- fused per-relation: score + softmax + aggregate ----------------
__global__ void __launch_bounds__(256) K_main(const int* __restrict__ trip,
                                              const float* __restrict__ attn_bin,
                                              const float* __restrict__ attn_vec,
                                              float* __restrict__ out) {
    __shared__ float P1s[128];
    __shared__ float vecS[128];
    __shared__ float binS[NUM_BIN * NUM_HEAD];
    __shared__ int   tailS[CAP];
    __shared__ float scoreS[CAP * NUM_HEAD];   // scores, then betas in-place
    __shared__ float wM[8 * 8], wS[8 * 8];
    __shared__ float mF[8], invS[8];
    __shared__ float accS[8 * 128];            // per-warp float4 partials

    int r = blockIdx.x;
    int tid = threadIdx.x;
    int start = g_off[r];
    int cnt = g_off[r + 1] - start;

    if (cnt == 0) {
        if (tid < 128) out[r * 128 + tid] = 0.f;
        return;
    }

    if (tid < 128) {
        P1s[tid]  = g_P1[r * 128 + tid];
        vecS[tid] = attn_vec[tid];
    }
    if (tid < NUM_BIN * NUM_HEAD) {
        float b = attn_bin[tid];
        binS[tid] = (b >= 0.f) ? b : NEG * b;
    }
    __syncthreads();

    int w = tid >> 5, lane = tid & 31;
    float m = -3.0e38f, s = 0.f;

    // ---- pass 1: scores + warp-local online softmax (warp per edge) ----
    for (int i = w; i < cnt; i += 8) {
        int e = g_sorted[start + i];
        int tail = trip[e * 3 + 1];
        int bin  = trip[e * 3 + 2];
        float4 p2 = *(const float4*)(g_P2 + (size_t)tail * 128 + lane * 4);
        float4 p1 = *(const float4*)(P1s + lane * 4);
        float4 v  = *(const float4*)(vecS + lane * 4);
        float x0 = p1.x + p2.x; x0 = (x0 >= 0.f) ? x0 : NEG * x0;
        float x1 = p1.y + p2.y; x1 = (x1 >= 0.f) ? x1 : NEG * x1;
        float x2 = p1.z + p2.z; x2 = (x2 >= 0.f) ? x2 : NEG * x2;
        float x3 = p1.w + p2.w; x3 = (x3 >= 0.f) ? x3 : NEG * x3;
        float part = x0 * v.x + x1 * v.y + x2 * v.z + x3 * v.w;
        part += __shfl_xor_sync(0xffffffffu, part, 1);
        part += __shfl_xor_sync(0xffffffffu, part, 2);
        float score = part + binS[bin * 8 + (lane >> 2)];
        if ((lane & 3) == 0) {           // one lane per head
            float mo = m;
            m = fmaxf(m, score);
            s = s * __expf(mo - m) + __expf(score - m);
        }
        float sc = __shfl_sync(0xffffffffu, score, (lane * 4) & 31);
        if (i < CAP) {
            if (lane < 8) scoreS[i * 8 + lane] = sc;
            if (lane == 0) tailS[i] = tail;
        } else {
            if (lane < 8) g_attn[(size_t)e * 8 + lane] = sc;
        }
    }
    if ((lane & 3) == 0) {
        wM[w * 8 + (lane >> 2)] = m;
        wS[w * 8 + (lane >> 2)] = s;
    }
    __syncthreads();

    // ---- cross-warp softmax merge ----
    if (tid < 8) {
        float M = -3.0e38f;
#pragma unroll
        for (int ww = 0; ww < 8; ww++) M = fmaxf(M, wM[ww * 8 + tid]);
        float S = 0.f;
#pragma unroll
        for (int ww = 0; ww < 8; ww++) S += wS[ww * 8 + tid] * __expf(wM[ww * 8 + tid] - M);
        mF[tid] = M;
        invS[tid] = 1.f / (S + 1e-16f);
    }
    __syncthreads();

    // ---- beta precompute in place (8 exps per edge, cooperative) ----
    int capped = (cnt < CAP) ? cnt : CAP;
    for (int idx = tid; idx < capped * 8; idx += 256) {
        int h = idx & 7;
        scoreS[idx] = __expf(scoreS[idx] - mF[h]) * invS[h];
    }
    __syncthreads();

    // ---- pass 2: warp-per-edge aggregation, float4 gathers ----
    int h4 = lane >> 2;                // head covering d = lane*4 .. lane*4+3
    float4 a4 = make_float4(0.f, 0.f, 0.f, 0.f);
    for (int i = w; i < cnt; i += 8) {
        float beta;
        int tail;
        if (i < CAP) {
            tail = tailS[i];
            beta = scoreS[i * 8 + h4];
        } else {
            int e = g_sorted[start + i];
            tail = trip[e * 3 + 1];
            beta = __expf(g_attn[(size_t)e * 8 + h4] - mF[h4]) * invS[h4];
        }
        float4 mv = *(const float4*)(g_M + (size_t)tail * 128 + lane * 4);
        a4.x = fmaf(beta, mv.x, a4.x);
        a4.y = fmaf(beta, mv.y, a4.y);
        a4.z = fmaf(beta, mv.z, a4.z);
        a4.w = fmaf(beta, mv.w, a4.w);
    }
    *(float4*)&accS[w * 128 + lane * 4] = a4;
    __syncthreads();
    if (tid < 128) {
        float sum = 0.f;
#pragma unroll
        for (int ww = 0; ww < 8; ww++) sum += accS[ww * 128 + tid];
        out[r * 128 + tid] = sum;
    }
}

// ---------------- launch ----------------
extern "C" void kernel_launch(void* const* d_in, const int* in_sizes, int n_in,
                              void* d_out, int out_size) {
    const float* emb  = (const float*)d_in[0];
    const int*   trip = (const int*)d_in[1];
    const float* apw  = (const float*)d_in[2];
    const float* apb  = (const float*)d_in[3];
    const float* abin = (const float*)d_in[4];
    const float* avec = (const float*)d_in[5];
    const float* agw  = (const float*)d_in[6];
    const float* agb  = (const float*)d_in[7];
    float* out = (float*)d_out;

    K_pre<<<(3 * DIM * DIM + 255) / 256, 256>>>(apw, agw);
    K_gemm<<<NUM_REL / 32, 256>>>(emb, apb, 0);        // P1 (+attn bias)
    K_gemm<<<NUM_REL / 32, 256>>>(emb, nullptr, 1);    // P2
    K_gemm<<<NUM_REL / 32, 256>>>(emb, agb, 2);        // M  (+aggr bias)
    K_hist<<<(NUM_EDGES + 255) / 256, 256>>>(trip);
    K_scan1<<<SCAN_B, 256>>>();
    K_scan2<<<1, 128>>>();
    K_scan3<<<SCAN_B, 256>>>();
    K_scatter<<<(NUM_EDGES + 255) / 256, 256>>>(trip);
    K_main<<<NUM_REL, 256>>>(trip, abin, avec, out);
}

// round 7
// speedup vs baseline: 1.2436x; 1.2436x over previous
#include <cuda_runtime.h>
#include <cuda_bf16.h>

#define NUM_REL   20000
#define NUM_EDGES 640000
#define DIM       128
#define NUM_HEAD  8
#define DIM_HID   16
#define NUM_BIN   10
#define NEG       0.2f
#define CAP       256   // per-relation shared score cache (cnt ~ Binom(640K,1/20K): mean 32)
#define SCAN_B    79    // ceil(20000/256)

// ---------------- device scratch (static: no allocs allowed) ----------------
__device__ float g_P1[NUM_REL * DIM];
__device__ float g_P2[NUM_REL * DIM];
__device__ float g_M [NUM_REL * DIM];
__device__ float g_attn[NUM_EDGES * NUM_HEAD];  // fallback only (cnt > CAP)
__device__ float g_Wt1[DIM * DIM];
__device__ float g_Wt2[DIM * DIM];
__device__ float g_Wt3[DIM * DIM];
__device__ int   g_cnt[NUM_REL];
__device__ int   g_off[NUM_REL + 1];
__device__ int   g_cur[NUM_REL];
__device__ int   g_sorted[NUM_EDGES];
__device__ int   g_bsum[SCAN_B + 1];

// ---------------- zero counts + weight transpose (merged) ----------------
__global__ void K_pre(const float* __restrict__ attn_w, const float* __restrict__ aggr_w) {
    int id = blockIdx.x * blockDim.x + threadIdx.x;
    if (id < NUM_REL) g_cnt[id] = 0;
    if (id >= 3 * DIM * DIM) return;
    int mtx = id / (DIM * DIM);
    int rem = id % (DIM * DIM);
    int j = rem / DIM, k = rem % DIM;
    if (mtx == 0)       g_Wt1[k * DIM + j] = attn_w[j * (2 * DIM) + k];
    else if (mtx == 1)  g_Wt2[k * DIM + j] = attn_w[j * (2 * DIM) + DIM + k];
    else                g_Wt3[k * DIM + j] = aggr_w[j * DIM + k];
}

__global__ void K_hist(const int* __restrict__ trip) {
    int e = blockIdx.x * blockDim.x + threadIdx.x;
    if (e < NUM_EDGES) atomicAdd(&g_cnt[trip[e * 3]], 1);
}

// ---------------- 3-phase parallel scan ----------------
__global__ void K_scan1() {           // SCAN_B blocks x 256: local scan
    __shared__ int sh[256];
    int tid = threadIdx.x;
    int i = blockIdx.x * 256 + tid;
    int v = (i < NUM_REL) ? g_cnt[i] : 0;
    sh[tid] = v;
    __syncthreads();
#pragma unroll
    for (int off = 1; off < 256; off <<= 1) {
        int t = (tid >= off) ? sh[tid - off] : 0;
        __syncthreads();
        sh[tid] += t;
        __syncthreads();
    }
    if (i < NUM_REL) g_off[i] = sh[tid] - v;          // local exclusive prefix
    if (tid == 255) g_bsum[blockIdx.x] = sh[255];     // block total
}

__global__ void K_scan2() {           // 1 block x 128: scan the 79 block sums
    __shared__ int sh[128];
    int tid = threadIdx.x;
    int v = (tid < SCAN_B) ? g_bsum[tid] : 0;
    sh[tid] = v;
    __syncthreads();
#pragma unroll
    for (int off = 1; off < 128; off <<= 1) {
        int t = (tid >= off) ? sh[tid - off] : 0;
        __syncthreads();
        sh[tid] += t;
        __syncthreads();
    }
    if (tid < SCAN_B) g_bsum[tid] = sh[tid] - v;      // exclusive base per block
    if (tid == 127) g_off[NUM_REL] = sh[127];         // grand total
}

__global__ void K_scan3() {           // SCAN_B blocks x 256: add base, init cursors
    int i = blockIdx.x * 256 + threadIdx.x;
    if (i < NUM_REL) {
        int o = g_off[i] + g_bsum[blockIdx.x];
        g_off[i] = o;
        g_cur[i] = o;
    }
}

__global__ void K_scatter(const int* __restrict__ trip) {
    int e = blockIdx.x * blockDim.x + threadIdx.x;
    if (e < NUM_EDGES) {
        int pos = atomicAdd(&g_cur[trip[e * 3]], 1);
        g_sorted[pos] = e;
    }
}

// ------- 20000x128x128 SGEMM (R4-measured 25us version, verbatim) -------
__global__ void K_gemm(const float* __restrict__ emb, const float* __restrict__ bias, int which) {
    const float* __restrict__ Wt = (which == 0) ? g_Wt1 : (which == 1) ? g_Wt2 : g_Wt3;
    float*       __restrict__ op = (which == 0) ? g_P1  : (which == 1) ? g_P2  : g_M;

    __shared__ float embS[32 * 128];
    __shared__ float WtS[32 * 132];   // [k_local][j] padded row 132 -> conflict-free LDS.128

    int tid = threadIdx.x;
    int rbase = blockIdx.x * 32;

    const float4* eg = (const float4*)(emb + (size_t)rbase * DIM);
#pragma unroll
    for (int i = 0; i < 4; i++)
        ((float4*)embS)[tid + i * 256] = eg[tid + i * 256];

    int jt = tid & 31, j0 = jt * 4;
    int rt = tid >> 5, r0 = rt * 4;

    float acc[4][4];
#pragma unroll
    for (int a = 0; a < 4; a++)
#pragma unroll
        for (int b = 0; b < 4; b++) acc[a][b] = 0.f;

    for (int kc = 0; kc < 4; kc++) {
        __syncthreads();
#pragma unroll
        for (int i = 0; i < 4; i++) {
            int v = tid + i * 256;
            int kl = v >> 5, jq = v & 31;
            *(float4*)&WtS[kl * 132 + jq * 4] = ((const float4*)Wt)[kc * 1024 + v];
        }
        __syncthreads();
#pragma unroll
        for (int kk = 0; kk < 32; kk++) {
            int k = kc * 32 + kk;
            float4 wv = *(float4*)&WtS[kk * 132 + j0];
            float e0 = embS[(r0 + 0) * 128 + k];
            float e1 = embS[(r0 + 1) * 128 + k];
            float e2 = embS[(r0 + 2) * 128 + k];
            float e3 = embS[(r0 + 3) * 128 + k];
            acc[0][0] = fmaf(e0, wv.x, acc[0][0]); acc[0][1] = fmaf(e0, wv.y, acc[0][1]);
            acc[0][2] = fmaf(e0, wv.z, acc[0][2]); acc[0][3] = fmaf(e0, wv.w, acc[0][3]);
            acc[1][0] = fmaf(e1, wv.x, acc[1][0]); acc[1][1] = fmaf(e1, wv.y, acc[1][1]);
            acc[1][2] = fmaf(e1, wv.z, acc[1][2]); acc[1][3] = fmaf(e1, wv.w, acc[1][3]);
            acc[2][0] = fmaf(e2, wv.x, acc[2][0]); acc[2][1] = fmaf(e2, wv.y, acc[2][1]);
            acc[2][2] = fmaf(e2, wv.z, acc[2][2]); acc[2][3] = fmaf(e2, wv.w, acc[2][3]);
            acc[3][0] = fmaf(e3, wv.x, acc[3][0]); acc[3][1] = fmaf(e3, wv.y, acc[3][1]);
            acc[3][2] = fmaf(e3, wv.z, acc[3][2]); acc[3][3] = fmaf(e3, wv.w, acc[3][3]);
        }
    }

    float4 bv = make_float4(0.f, 0.f, 0.f, 0.f);
    if (bias) bv = *(const float4*)(bias + j0);
#pragma unroll
    for (int a = 0; a < 4; a++) {
        float4 o;
        o.x = acc[a][0] + bv.x; o.y = acc[a][1] + bv.y;
        o.z = acc[a][2] + bv.z; o.w = acc[a][3] + bv.w;
        *(float4*)&op[(size_t)(rbase + r0 + a) * DIM + j0] = o;
    }
}

// ------- fused per-relation: score + softmax + aggregate (R5 K_main: beta-precompute, 2-slot agg) -------
__global__ void K_main(const int* __restrict__ trip,
                       const float* __restrict__ attn_bin,
                       const float* __restrict__ attn_vec,
                       float* __restrict__ out) {
    __shared__ float P1s[128];
    __shared__ float vecS[128];
    __shared__ float binS[NUM_BIN * NUM_HEAD];
    __shared__ int   tailS[CAP];
    __shared__ float scoreS[CAP * NUM_HEAD];   // scores, then betas in-place
    __shared__ float wM[8 * 8], wS[8 * 8];
    __shared__ float mF[8], invS[8];
    __shared__ float accS[256];

    int r = blockIdx.x;
    int tid = threadIdx.x;
    int start = g_off[r];
    int cnt = g_off[r + 1] - start;

    if (cnt == 0) {
        if (tid < 128) out[r * 128 + tid] = 0.f;
        return;
    }

    if (tid < 128) {
        P1s[tid]  = g_P1[r * 128 + tid];
        vecS[tid] = attn_vec[tid];
    }
    if (tid < NUM_BIN * NUM_HEAD) {
        float b = attn_bin[tid];
        binS[tid] = (b >= 0.f) ? b : NEG * b;
    }
    __syncthreads();

    int w = tid >> 5, lane = tid & 31;
    float m = -3.0e38f, s = 0.f;

    // ---- pass 1: scores + warp-local online softmax (warp per edge) ----
    for (int i = w; i < cnt; i += 8) {
        int e = g_sorted[start + i];
        int tail = trip[e * 3 + 1];
        int bin  = trip[e * 3 + 2];
        float4 p2 = *(const float4*)(g_P2 + (size_t)tail * 128 + lane * 4);
        float4 p1 = *(const float4*)(P1s + lane * 4);
        float4 v  = *(const float4*)(vecS + lane * 4);
        float x0 = p1.x + p2.x; x0 = (x0 >= 0.f) ? x0 : NEG * x0;
        float x1 = p1.y + p2.y; x1 = (x1 >= 0.f) ? x1 : NEG * x1;
        float x2 = p1.z + p2.z; x2 = (x2 >= 0.f) ? x2 : NEG * x2;
        float x3 = p1.w + p2.w; x3 = (x3 >= 0.f) ? x3 : NEG * x3;
        float part = x0 * v.x + x1 * v.y + x2 * v.z + x3 * v.w;
        part += __shfl_xor_sync(0xffffffffu, part, 1);
        part += __shfl_xor_sync(0xffffffffu, part, 2);
        float score = part + binS[bin * 8 + (lane >> 2)];
        if ((lane & 3) == 0) {           // one lane per head
            float mo = m;
            m = fmaxf(m, score);
            s = s * __expf(mo - m) + __expf(score - m);
        }
        float sc = __shfl_sync(0xffffffffu, score, (lane * 4) & 31);
        if (i < CAP) {
            if (lane < 8) scoreS[i * 8 + lane] = sc;
            if (lane == 0) tailS[i] = tail;
        } else {
            if (lane < 8) g_attn[(size_t)e * 8 + lane] = sc;
        }
    }
    if ((lane & 3) == 0) {
        wM[w * 8 + (lane >> 2)] = m;
        wS[w * 8 + (lane >> 2)] = s;
    }
    __syncthreads();

    // ---- cross-warp softmax merge ----
    if (tid < 8) {
        float M = -3.0e38f;
#pragma unroll
        for (int ww = 0; ww < 8; ww++) M = fmaxf(M, wM[ww * 8 + tid]);
        float S = 0.f;
#pragma unroll
        for (int ww = 0; ww < 8; ww++) S += wS[ww * 8 + tid] * __expf(wM[ww * 8 + tid] - M);
        mF[tid] = M;
        invS[tid] = 1.f / (S + 1e-16f);
    }
    __syncthreads();

    // ---- beta precompute in place (8 exps per edge, cooperative) ----
    int capped = (cnt < CAP) ? cnt : CAP;
    for (int idx = tid; idx < capped * 8; idx += 256) {
        int h = idx & 7;
        scoreS[idx] = __expf(scoreS[idx] - mF[h]) * invS[h];
    }
    __syncthreads();

    // ---- pass 2: 2-slot aggregation, per-thread LDG.32 (high MLP) ----
    int half = tid >> 7;
    int d = tid & 127;
    int h = d >> 4;
    float mh = mF[h], iv = invS[h];
    float acc = 0.f;
#pragma unroll 2
    for (int i = half; i < cnt; i += 2) {
        float beta;
        int tail;
        if (i < CAP) {
            tail = tailS[i];
            beta = scoreS[i * 8 + h];
        } else {
            int e = g_sorted[start + i];
            tail = trip[e * 3 + 1];
            beta = __expf(g_attn[(size_t)e * 8 + h] - mh) * iv;
        }
        acc = fmaf(beta, g_M[(size_t)tail * 128 + d], acc);
    }
    accS[tid] = acc;
    __syncthreads();
    if (tid < 128) out[r * 128 + tid] = accS[tid] + accS[tid + 128];
}

// ---------------- launch ----------------
extern "C" void kernel_launch(void* const* d_in, const int* in_sizes, int n_in,
                              void* d_out, int out_size) {
    const float* emb  = (const float*)d_in[0];
    const int*   trip = (const int*)d_in[1];
    const float* apw  = (const float*)d_in[2];
    const float* apb  = (const float*)d_in[3];
    const float* abin = (const float*)d_in[4];
    const float* avec = (const float*)d_in[5];
    const float* agw  = (const float*)d_in[6];
    const float* agb  = (const float*)d_in[7];
    float* out = (float*)d_out;

    K_pre<<<(3 * DIM * DIM + 255) / 256, 256>>>(apw, agw);
    K_gemm<<<NUM_REL / 32, 256>>>(emb, apb, 0);        // P1 (+attn bias)
    K_gemm<<<NUM_REL / 32, 256>>>(emb, nullptr, 1);    // P2
    K_gemm<<<NUM_REL / 32, 256>>>(emb, agb, 2);        // M  (+aggr bias)
    K_hist<<<(NUM_EDGES + 255) / 256, 256>>>(trip);
    K_scan1<<<SCAN_B, 256>>>();
    K_scan2<<<1, 128>>>();
    K_scan3<<<SCAN_B, 256>>>();
    K_scatter<<<(NUM_EDGES + 255) / 256, 256>>>(trip);
    K_main<<<NUM_REL, 256>>>(trip, abin, avec, out);
}

// round 8
// speedup vs baseline: 1.3147x; 1.0572x over previous
#include <cuda_runtime.h>
#include <cuda_bf16.h>

#define NUM_REL   20000
#define NUM_EDGES 640000
#define DIM       128
#define NUM_HEAD  8
#define DIM_HID   16
#define NUM_BIN   10
#define NEG       0.2f
#define CAP       256   // per-relation shared score cache (cnt ~ Binom(640K,1/20K): mean 32)
#define SCAN_B    79    // ceil(20000/256)

// ---------------- device scratch (static: no allocs allowed) ----------------
__device__ float g_P1[NUM_REL * DIM];
__device__ float g_P2[NUM_REL * DIM];
__device__ float g_M [NUM_REL * DIM];
__device__ float g_attn[NUM_EDGES * NUM_HEAD];  // fallback only (cnt > CAP), indexed by sorted pos
__device__ float g_Wt1[DIM * DIM];
__device__ float g_Wt2[DIM * DIM];
__device__ float g_Wt3[DIM * DIM];
__device__ int   g_cnt[NUM_REL];
__device__ int   g_off[NUM_REL + 1];
__device__ int   g_cur[NUM_REL];
__device__ int   g_sorted[NUM_EDGES];   // packed: tail | (bin << 20)
__device__ int   g_bsum[SCAN_B + 1];

// ---------------- zero counts + weight transpose (merged) ----------------
__global__ void K_pre(const float* __restrict__ attn_w, const float* __restrict__ aggr_w) {
    int id = blockIdx.x * blockDim.x + threadIdx.x;
    if (id < NUM_REL) g_cnt[id] = 0;
    if (id >= 3 * DIM * DIM) return;
    int mtx = id / (DIM * DIM);
    int rem = id % (DIM * DIM);
    int j = rem / DIM, k = rem % DIM;
    if (mtx == 0)       g_Wt1[k * DIM + j] = attn_w[j * (2 * DIM) + k];
    else if (mtx == 1)  g_Wt2[k * DIM + j] = attn_w[j * (2 * DIM) + DIM + k];
    else                g_Wt3[k * DIM + j] = aggr_w[j * DIM + k];
}

__global__ void K_hist(const int* __restrict__ trip) {
    int e = blockIdx.x * blockDim.x + threadIdx.x;
    if (e < NUM_EDGES) atomicAdd(&g_cnt[trip[e * 3]], 1);
}

// ---------------- 3-phase parallel scan ----------------
__global__ void K_scan1() {
    __shared__ int sh[256];
    int tid = threadIdx.x;
    int i = blockIdx.x * 256 + tid;
    int v = (i < NUM_REL) ? g_cnt[i] : 0;
    sh[tid] = v;
    __syncthreads();
#pragma unroll
    for (int off = 1; off < 256; off <<= 1) {
        int t = (tid >= off) ? sh[tid - off] : 0;
        __syncthreads();
        sh[tid] += t;
        __syncthreads();
    }
    if (i < NUM_REL) g_off[i] = sh[tid] - v;
    if (tid == 255) g_bsum[blockIdx.x] = sh[255];
}

__global__ void K_scan2() {
    __shared__ int sh[128];
    int tid = threadIdx.x;
    int v = (tid < SCAN_B) ? g_bsum[tid] : 0;
    sh[tid] = v;
    __syncthreads();
#pragma unroll
    for (int off = 1; off < 128; off <<= 1) {
        int t = (tid >= off) ? sh[tid - off] : 0;
        __syncthreads();
        sh[tid] += t;
        __syncthreads();
    }
    if (tid < SCAN_B) g_bsum[tid] = sh[tid] - v;
    if (tid == 127) g_off[NUM_REL] = sh[127];
}

__global__ void K_scan3() {
    int i = blockIdx.x * 256 + threadIdx.x;
    if (i < NUM_REL) {
        int o = g_off[i] + g_bsum[blockIdx.x];
        g_off[i] = o;
        g_cur[i] = o;
    }
}

// scatter PACKED payload: tail | bin<<20  (tail < 2^15, bin < 2^4)
__global__ void K_scatter(const int* __restrict__ trip) {
    int e = blockIdx.x * blockDim.x + threadIdx.x;
    if (e < NUM_EDGES) {
        int h    = trip[e * 3];
        int tail = trip[e * 3 + 1];
        int bin  = trip[e * 3 + 2];
        int pos = atomicAdd(&g_cur[h], 1);
        g_sorted[pos] = tail | (bin << 20);
    }
}

// ------- 20000x128x128 SGEMM (R4-measured body verbatim); grid.y selects matrix -------
__global__ void K_gemm(const float* __restrict__ emb,
                       const float* __restrict__ apb,
                       const float* __restrict__ agb) {
    int which = blockIdx.y;
    const float* __restrict__ Wt = (which == 0) ? g_Wt1 : (which == 1) ? g_Wt2 : g_Wt3;
    float*       __restrict__ op = (which == 0) ? g_P1  : (which == 1) ? g_P2  : g_M;
    const float* bias = (which == 0) ? apb : (which == 1) ? (const float*)0 : agb;

    __shared__ float embS[32 * 128];
    __shared__ float WtS[32 * 132];   // padded row 132 -> conflict-free LDS.128

    int tid = threadIdx.x;
    int rbase = blockIdx.x * 32;

    const float4* eg = (const float4*)(emb + (size_t)rbase * DIM);
#pragma unroll
    for (int i = 0; i < 4; i++)
        ((float4*)embS)[tid + i * 256] = eg[tid + i * 256];

    int jt = tid & 31, j0 = jt * 4;
    int rt = tid >> 5, r0 = rt * 4;

    float acc[4][4];
#pragma unroll
    for (int a = 0; a < 4; a++)
#pragma unroll
        for (int b = 0; b < 4; b++) acc[a][b] = 0.f;

    for (int kc = 0; kc < 4; kc++) {
        __syncthreads();
#pragma unroll
        for (int i = 0; i < 4; i++) {
            int v = tid + i * 256;
            int kl = v >> 5, jq = v & 31;
            *(float4*)&WtS[kl * 132 + jq * 4] = ((const float4*)Wt)[kc * 1024 + v];
        }
        __syncthreads();
#pragma unroll
        for (int kk = 0; kk < 32; kk++) {
            int k = kc * 32 + kk;
            float4 wv = *(float4*)&WtS[kk * 132 + j0];
            float e0 = embS[(r0 + 0) * 128 + k];
            float e1 = embS[(r0 + 1) * 128 + k];
            float e2 = embS[(r0 + 2) * 128 + k];
            float e3 = embS[(r0 + 3) * 128 + k];
            acc[0][0] = fmaf(e0, wv.x, acc[0][0]); acc[0][1] = fmaf(e0, wv.y, acc[0][1]);
            acc[0][2] = fmaf(e0, wv.z, acc[0][2]); acc[0][3] = fmaf(e0, wv.w, acc[0][3]);
            acc[1][0] = fmaf(e1, wv.x, acc[1][0]); acc[1][1] = fmaf(e1, wv.y, acc[1][1]);
            acc[1][2] = fmaf(e1, wv.z, acc[1][2]); acc[1][3] = fmaf(e1, wv.w, acc[1][3]);
            acc[2][0] = fmaf(e2, wv.x, acc[2][0]); acc[2][1] = fmaf(e2, wv.y, acc[2][1]);
            acc[2][2] = fmaf(e2, wv.z, acc[2][2]); acc[2][3] = fmaf(e2, wv.w, acc[2][3]);
            acc[3][0] = fmaf(e3, wv.x, acc[3][0]); acc[3][1] = fmaf(e3, wv.y, acc[3][1]);
            acc[3][2] = fmaf(e3, wv.z, acc[3][2]); acc[3][3] = fmaf(e3, wv.w, acc[3][3]);
        }
    }

    float4 bv = make_float4(0.f, 0.f, 0.f, 0.f);
    if (bias) bv = *(const float4*)(bias + j0);
#pragma unroll
    for (int a = 0; a < 4; a++) {
        float4 o;
        o.x = acc[a][0] + bv.x; o.y = acc[a][1] + bv.y;
        o.z = acc[a][2] + bv.z; o.w = acc[a][3] + bv.w;
        *(float4*)&op[(size_t)(rbase + r0 + a) * DIM + j0] = o;
    }
}

// ------- fused per-relation: score + softmax + aggregate -------
__global__ void K_main(const float* __restrict__ attn_bin,
                       const float* __restrict__ attn_vec,
                       float* __restrict__ out) {
    __shared__ float P1s[128];
    __shared__ float vecS[128];
    __shared__ float binS[NUM_BIN * NUM_HEAD];
    __shared__ int   tailS[CAP];
    __shared__ float scoreS[CAP * NUM_HEAD];   // scores, then betas in-place
    __shared__ float wM[8 * 8], wS[8 * 8];
    __shared__ float mF[8], invS[8];
    __shared__ float accS[256];

    int r = blockIdx.x;
    int tid = threadIdx.x;
    int start = g_off[r];
    int cnt = g_off[r + 1] - start;

    if (cnt == 0) {
        if (tid < 128) out[r * 128 + tid] = 0.f;
        return;
    }

    if (tid < 128) {
        P1s[tid]  = g_P1[r * 128 + tid];
        vecS[tid] = attn_vec[tid];
    }
    if (tid < NUM_BIN * NUM_HEAD) {
        float b = attn_bin[tid];
        binS[tid] = (b >= 0.f) ? b : NEG * b;
    }
    __syncthreads();

    int w = tid >> 5, lane = tid & 31;
    float m = -3.0e38f, s = 0.f;

    // ---- pass 1: scores + warp-local online softmax (warp per edge) ----
    for (int i = w; i < cnt; i += 8) {
        int val  = g_sorted[start + i];         // packed: one gather level only
        int tail = val & 0xFFFFF;
        int bin  = val >> 20;
        float4 p2 = *(const float4*)(g_P2 + (size_t)tail * 128 + lane * 4);
        float4 p1 = *(const float4*)(P1s + lane * 4);
        float4 v  = *(const float4*)(vecS + lane * 4);
        float x0 = p1.x + p2.x; x0 = (x0 >= 0.f) ? x0 : NEG * x0;
        float x1 = p1.y + p2.y; x1 = (x1 >= 0.f) ? x1 : NEG * x1;
        float x2 = p1.z + p2.z; x2 = (x2 >= 0.f) ? x2 : NEG * x2;
        float x3 = p1.w + p2.w; x3 = (x3 >= 0.f) ? x3 : NEG * x3;
        float part = x0 * v.x + x1 * v.y + x2 * v.z + x3 * v.w;
        part += __shfl_xor_sync(0xffffffffu, part, 1);
        part += __shfl_xor_sync(0xffffffffu, part, 2);
        float score = part + binS[bin * 8 + (lane >> 2)];
        if ((lane & 3) == 0) {           // one lane per head
            float mo = m;
            m = fmaxf(m, score);
            s = s * __expf(mo - m) + __expf(score - m);
        }
        float sc = __shfl_sync(0xffffffffu, score, (lane * 4) & 31);
        if (i < CAP) {
            if (lane < 8) scoreS[i * 8 + lane] = sc;
            if (lane == 0) tailS[i] = tail;
        } else {
            if (lane < 8) g_attn[(size_t)(start + i) * 8 + lane] = sc;  // by sorted pos
        }
    }
    if ((lane & 3) == 0) {
        wM[w * 8 + (lane >> 2)] = m;
        wS[w * 8 + (lane >> 2)] = s;
    }
    __syncthreads();

    // ---- cross-warp softmax merge ----
    if (tid < 8) {
        float M = -3.0e38f;
#pragma unroll
        for (int ww = 0; ww < 8; ww++) M = fmaxf(M, wM[ww * 8 + tid]);
        float S = 0.f;
#pragma unroll
        for (int ww = 0; ww < 8; ww++) S += wS[ww * 8 + tid] * __expf(wM[ww * 8 + tid] - M);
        mF[tid] = M;
        invS[tid] = 1.f / (S + 1e-16f);
    }
    __syncthreads();

    // ---- beta precompute in place (cooperative) ----
    int capped = (cnt < CAP) ? cnt : CAP;
    for (int idx = tid; idx < capped * 8; idx += 256) {
        int h = idx & 7;
        scoreS[idx] = __expf(scoreS[idx] - mF[h]) * invS[h];
    }
    __syncthreads();

    // ---- pass 2: 2-slot aggregation, per-thread LDG.32 (high MLP) ----
    int half = tid >> 7;
    int d = tid & 127;
    int h = d >> 4;
    float mh = mF[h], iv = invS[h];
    float acc = 0.f;
#pragma unroll 2
    for (int i = half; i < cnt; i += 2) {
        float beta;
        int tail;
        if (i < CAP) {
            tail = tailS[i];
            beta = scoreS[i * 8 + h];
        } else {
            tail = g_sorted[start + i] & 0xFFFFF;
            beta = __expf(g_attn[(size_t)(start + i) * 8 + h] - mh) * iv;
        }
        acc = fmaf(beta, g_M[(size_t)tail * 128 + d], acc);
    }
    accS[tid] = acc;
    __syncthreads();
    if (tid < 128) out[r * 128 + tid] = accS[tid] + accS[tid + 128];
}

// ---------------- launch ----------------
extern "C" void kernel_launch(void* const* d_in, const int* in_sizes, int n_in,
                              void* d_out, int out_size) {
    const float* emb  = (const float*)d_in[0];
    const int*   trip = (const int*)d_in[1];
    const float* apw  = (const float*)d_in[2];
    const float* apb  = (const float*)d_in[3];
    const float* abin = (const float*)d_in[4];
    const float* avec = (const float*)d_in[5];
    const float* agw  = (const float*)d_in[6];
    const float* agb  = (const float*)d_in[7];
    float* out = (float*)d_out;

    K_pre<<<(3 * DIM * DIM + 255) / 256, 256>>>(apw, agw);
    K_gemm<<<dim3(NUM_REL / 32, 3), 256>>>(emb, apb, agb);   // all three matrices, one launch
    K_hist<<<(NUM_EDGES + 255) / 256, 256>>>(trip);
    K_scan1<<<SCAN_B, 256>>>();
    K_scan2<<<1, 128>>>();
    K_scan3<<<SCAN_B, 256>>>();
    K_scatter<<<(NUM_EDGES + 255) / 256, 256>>>(trip);
    K_main<<<NUM_REL, 256>>>(abin, avec, out);
}

// round 9
// speedup vs baseline: 1.8872x; 1.4354x over previous
#include <cuda_runtime.h>
#include <cuda_bf16.h>

#define NUM_REL   20000
#define NUM_EDGES 640000
#define DIM       128
#define NUM_HEAD  8
#define DIM_HID   16
#define NUM_BIN   10
#define NEG       0.2f
#define SCAN_B    79    // ceil(20000/256)

// ---------------- device scratch (static: no allocs allowed) ----------------
__device__ float g_P1[NUM_REL * DIM];
__device__ float g_P2[NUM_REL * DIM];
__device__ float g_M [NUM_REL * DIM];
__device__ float g_Wt1[DIM * DIM];
__device__ float g_Wt2[DIM * DIM];
__device__ float g_Wt3[DIM * DIM];
__device__ int   g_cnt[NUM_REL];
__device__ int   g_off[NUM_REL + 1];
__device__ int   g_cur[NUM_REL];
__device__ int   g_sorted[NUM_EDGES];   // packed: tail | (bin << 20)
__device__ int   g_bsum[SCAN_B + 1];

// ---------------- zero counts + weight transpose (merged) ----------------
__global__ void K_pre(const float* __restrict__ attn_w, const float* __restrict__ aggr_w) {
    int id = blockIdx.x * blockDim.x + threadIdx.x;
    if (id < NUM_REL) g_cnt[id] = 0;
    if (id >= 3 * DIM * DIM) return;
    int mtx = id / (DIM * DIM);
    int rem = id % (DIM * DIM);
    int j = rem / DIM, k = rem % DIM;
    if (mtx == 0)       g_Wt1[k * DIM + j] = attn_w[j * (2 * DIM) + k];
    else if (mtx == 1)  g_Wt2[k * DIM + j] = attn_w[j * (2 * DIM) + DIM + k];
    else                g_Wt3[k * DIM + j] = aggr_w[j * DIM + k];
}

__global__ void K_hist(const int* __restrict__ trip) {
    int e = blockIdx.x * blockDim.x + threadIdx.x;
    if (e < NUM_EDGES) atomicAdd(&g_cnt[trip[e * 3]], 1);
}

// ---------------- 3-phase parallel scan ----------------
__global__ void K_scan1() {
    __shared__ int sh[256];
    int tid = threadIdx.x;
    int i = blockIdx.x * 256 + tid;
    int v = (i < NUM_REL) ? g_cnt[i] : 0;
    sh[tid] = v;
    __syncthreads();
#pragma unroll
    for (int off = 1; off < 256; off <<= 1) {
        int t = (tid >= off) ? sh[tid - off] : 0;
        __syncthreads();
        sh[tid] += t;
        __syncthreads();
    }
    if (i < NUM_REL) g_off[i] = sh[tid] - v;
    if (tid == 255) g_bsum[blockIdx.x] = sh[255];
}

__global__ void K_scan2() {
    __shared__ int sh[128];
    int tid = threadIdx.x;
    int v = (tid < SCAN_B) ? g_bsum[tid] : 0;
    sh[tid] = v;
    __syncthreads();
#pragma unroll
    for (int off = 1; off < 128; off <<= 1) {
        int t = (tid >= off) ? sh[tid - off] : 0;
        __syncthreads();
        sh[tid] += t;
        __syncthreads();
    }
    if (tid < SCAN_B) g_bsum[tid] = sh[tid] - v;
    if (tid == 127) g_off[NUM_REL] = sh[127];
}

__global__ void K_scan3() {
    int i = blockIdx.x * 256 + threadIdx.x;
    if (i < NUM_REL) {
        int o = g_off[i] + g_bsum[blockIdx.x];
        g_off[i] = o;
        g_cur[i] = o;
    }
}

// scatter PACKED payload: tail | bin<<20  (tail < 2^15, bin < 2^4)
__global__ void K_scatter(const int* __restrict__ trip) {
    int e = blockIdx.x * blockDim.x + threadIdx.x;
    if (e < NUM_EDGES) {
        int h    = trip[e * 3];
        int tail = trip[e * 3 + 1];
        int bin  = trip[e * 3 + 2];
        int pos = atomicAdd(&g_cur[h], 1);
        g_sorted[pos] = tail | (bin << 20);
    }
}

// ------- 20000x128x128 SGEMM (R4-measured body verbatim); grid.y selects matrix -------
__global__ void K_gemm(const float* __restrict__ emb,
                       const float* __restrict__ apb,
                       const float* __restrict__ agb) {
    int which = blockIdx.y;
    const float* __restrict__ Wt = (which == 0) ? g_Wt1 : (which == 1) ? g_Wt2 : g_Wt3;
    float*       __restrict__ op = (which == 0) ? g_P1  : (which == 1) ? g_P2  : g_M;
    const float* bias = (which == 0) ? apb : (which == 1) ? (const float*)0 : agb;

    __shared__ float embS[32 * 128];
    __shared__ float WtS[32 * 132];   // padded row 132 -> conflict-free LDS.128

    int tid = threadIdx.x;
    int rbase = blockIdx.x * 32;

    const float4* eg = (const float4*)(emb + (size_t)rbase * DIM);
#pragma unroll
    for (int i = 0; i < 4; i++)
        ((float4*)embS)[tid + i * 256] = eg[tid + i * 256];

    int jt = tid & 31, j0 = jt * 4;
    int rt = tid >> 5, r0 = rt * 4;

    float acc[4][4];
#pragma unroll
    for (int a = 0; a < 4; a++)
#pragma unroll
        for (int b = 0; b < 4; b++) acc[a][b] = 0.f;

    for (int kc = 0; kc < 4; kc++) {
        __syncthreads();
#pragma unroll
        for (int i = 0; i < 4; i++) {
            int v = tid + i * 256;
            int kl = v >> 5, jq = v & 31;
            *(float4*)&WtS[kl * 132 + jq * 4] = ((const float4*)Wt)[kc * 1024 + v];
        }
        __syncthreads();
#pragma unroll
        for (int kk = 0; kk < 32; kk++) {
            int k = kc * 32 + kk;
            float4 wv = *(float4*)&WtS[kk * 132 + j0];
            float e0 = embS[(r0 + 0) * 128 + k];
            float e1 = embS[(r0 + 1) * 128 + k];
            float e2 = embS[(r0 + 2) * 128 + k];
            float e3 = embS[(r0 + 3) * 128 + k];
            acc[0][0] = fmaf(e0, wv.x, acc[0][0]); acc[0][1] = fmaf(e0, wv.y, acc[0][1]);
            acc[0][2] = fmaf(e0, wv.z, acc[0][2]); acc[0][3] = fmaf(e0, wv.w, acc[0][3]);
            acc[1][0] = fmaf(e1, wv.x, acc[1][0]); acc[1][1] = fmaf(e1, wv.y, acc[1][1]);
            acc[1][2] = fmaf(e1, wv.z, acc[1][2]); acc[1][3] = fmaf(e1, wv.w, acc[1][3]);
            acc[2][0] = fmaf(e2, wv.x, acc[2][0]); acc[2][1] = fmaf(e2, wv.y, acc[2][1]);
            acc[2][2] = fmaf(e2, wv.z, acc[2][2]); acc[2][3] = fmaf(e2, wv.w, acc[2][3]);
            acc[3][0] = fmaf(e3, wv.x, acc[3][0]); acc[3][1] = fmaf(e3, wv.y, acc[3][1]);
            acc[3][2] = fmaf(e3, wv.z, acc[3][2]); acc[3][3] = fmaf(e3, wv.w, acc[3][3]);
        }
    }

    float4 bv = make_float4(0.f, 0.f, 0.f, 0.f);
    if (bias) bv = *(const float4*)(bias + j0);
#pragma unroll
    for (int a = 0; a < 4; a++) {
        float4 o;
        o.x = acc[a][0] + bv.x; o.y = acc[a][1] + bv.y;
        o.z = acc[a][2] + bv.z; o.w = acc[a][3] + bv.w;
        *(float4*)&op[(size_t)(rbase + r0 + a) * DIM + j0] = o;
    }
}

// ------- single-pass per-relation: online softmax-weighted aggregation -------
__global__ void K_main(const float* __restrict__ attn_bin,
                       const float* __restrict__ attn_vec,
                       float* __restrict__ out) {
    __shared__ float P1s[128];
    __shared__ float vecS[128];
    __shared__ float binS[NUM_BIN * NUM_HEAD];
    __shared__ float wM[64], wS[64], fS[64];   // [warp][head]
    __shared__ float mF[8], invS[8];
    __shared__ float accS[8 * 128];            // [warp][dim]

    int r = blockIdx.x;
    int tid = threadIdx.x;
    int start = g_off[r];
    int cnt = g_off[r + 1] - start;

    if (cnt == 0) {
        if (tid < 128) out[r * 128 + tid] = 0.f;
        return;
    }

    if (tid < 128) {
        P1s[tid]  = g_P1[r * 128 + tid];
        vecS[tid] = attn_vec[tid];
    }
    if (tid < NUM_BIN * NUM_HEAD) {
        float b = attn_bin[tid];
        binS[tid] = (b >= 0.f) ? b : NEG * b;
    }
    __syncthreads();

    int w = tid >> 5, lane = tid & 31, h = lane >> 2;
    float4 p1 = *(const float4*)(P1s + lane * 4);   // loop-invariant, in registers
    float4 v  = *(const float4*)(vecS + lane * 4);

    float m = -3.0e38f, s = 0.f;
    float4 acc = make_float4(0.f, 0.f, 0.f, 0.f);

    // ---- single pass: score, online softmax, and aggregation together ----
#pragma unroll 2
    for (int i = w; i < cnt; i += 8) {
        int val  = g_sorted[start + i];
        int tail = val & 0xFFFFF;
        int bin  = val >> 20;
        const float* rowP2 = g_P2 + (size_t)tail * 128 + lane * 4;
        const float* rowM  = g_M  + (size_t)tail * 128 + lane * 4;
        float4 p2 = *(const float4*)rowP2;     // two independent LDG.128 in flight
        float4 mv = *(const float4*)rowM;
        float x0 = p1.x + p2.x; x0 = (x0 >= 0.f) ? x0 : NEG * x0;
        float x1 = p1.y + p2.y; x1 = (x1 >= 0.f) ? x1 : NEG * x1;
        float x2 = p1.z + p2.z; x2 = (x2 >= 0.f) ? x2 : NEG * x2;
        float x3 = p1.w + p2.w; x3 = (x3 >= 0.f) ? x3 : NEG * x3;
        float part = x0 * v.x + x1 * v.y + x2 * v.z + x3 * v.w;
        part += __shfl_xor_sync(0xffffffffu, part, 1);
        part += __shfl_xor_sync(0xffffffffu, part, 2);   // all 4 lanes of head group have the sum
        float score = part + binS[bin * 8 + h];
        if (score > m) {                                 // rare (~ln(cnt) times per head)
            float c = __expf(m - score);
            s *= c;
            acc.x *= c; acc.y *= c; acc.z *= c; acc.w *= c;
            m = score;
        }
        float wt = __expf(score - m);
        s += wt;
        acc.x = fmaf(wt, mv.x, acc.x);
        acc.y = fmaf(wt, mv.y, acc.y);
        acc.z = fmaf(wt, mv.z, acc.z);
        acc.w = fmaf(wt, mv.w, acc.w);
    }

    if ((lane & 3) == 0) {        // m,s replicated within head group; one writer
        wM[w * 8 + h] = m;
        wS[w * 8 + h] = s;
    }
    *(float4*)&accS[w * 128 + lane * 4] = acc;
    __syncthreads();

    // ---- cross-warp merge ----
    if (tid < 8) {
        float M = -3.0e38f;
#pragma unroll
        for (int ww = 0; ww < 8; ww++) M = fmaxf(M, wM[ww * 8 + tid]);
        mF[tid] = M;
    }
    __syncthreads();
    if (tid < 64) fS[tid] = __expf(wM[tid] - mF[tid & 7]);   // f[w][h]
    __syncthreads();
    if (tid < 8) {
        float S = 0.f;
#pragma unroll
        for (int ww = 0; ww < 8; ww++) S += wS[ww * 8 + tid] * fS[ww * 8 + tid];
        invS[tid] = 1.f / (S + 1e-16f);
    }
    __syncthreads();
    if (tid < 128) {
        int hh = tid >> 4;
        float sum = 0.f;
#pragma unroll
        for (int ww = 0; ww < 8; ww++) sum += accS[ww * 128 + tid] * fS[ww * 8 + hh];
        out[r * 128 + tid] = sum * invS[hh];
    }
}

// ---------------- launch ----------------
extern "C" void kernel_launch(void* const* d_in, const int* in_sizes, int n_in,
                              void* d_out, int out_size) {
    const float* emb  = (const float*)d_in[0];
    const int*   trip = (const int*)d_in[1];
    const float* apw  = (const float*)d_in[2];
    const float* apb  = (const float*)d_in[3];
    const float* abin = (const float*)d_in[4];
    const float* avec = (const float*)d_in[5];
    const float* agw  = (const float*)d_in[6];
    const float* agb  = (const float*)d_in[7];
    float* out = (float*)d_out;

    K_pre<<<(3 * DIM * DIM + 255) / 256, 256>>>(apw, agw);
    K_gemm<<<dim3(NUM_REL / 32, 3), 256>>>(emb, apb, agb);
    K_hist<<<(NUM_EDGES + 255) / 256, 256>>>(trip);
    K_scan1<<<SCAN_B, 256>>>();
    K_scan2<<<1, 128>>>();
    K_scan3<<<SCAN_B, 256>>>();
    K_scatter<<<(NUM_EDGES + 255) / 256, 256>>>(trip);
    K_main<<<NUM_REL, 256>>>(abin, avec, out);
}

// round 10
// speedup vs baseline: 2.2295x; 1.1814x over previous
#include <cuda_runtime.h>
#include <cuda_bf16.h>

#define NUM_REL   20000
#define NUM_EDGES 640000
#define DIM       128
#define NUM_HEAD  8
#define DIM_HID   16
#define NUM_BIN   10
#define NEG       0.2f
#define SCAN_B    79    // ceil(20000/256)

// ---------------- device scratch (static: no allocs allowed) ----------------
__device__ float g_P1[NUM_REL * DIM];
__device__ float g_P2[NUM_REL * DIM];
__device__ float g_M [NUM_REL * DIM];
__device__ float g_Wt1[DIM * DIM];
__device__ float g_Wt2[DIM * DIM];
__device__ float g_Wt3[DIM * DIM];
__device__ int   g_cnt[NUM_REL];
__device__ int   g_off[NUM_REL + 1];
__device__ int   g_cur[NUM_REL];
__device__ int   g_sorted[NUM_EDGES];   // packed: tail | (bin << 20)
__device__ int   g_bsum[SCAN_B + 1];

// ---------------- zero counts + weight transpose (merged) ----------------
__global__ void K_pre(const float* __restrict__ attn_w, const float* __restrict__ aggr_w) {
    int id = blockIdx.x * blockDim.x + threadIdx.x;
    if (id >= 3 * DIM * DIM) return;
    int mtx = id / (DIM * DIM);
    int rem = id % (DIM * DIM);
    int j = rem / DIM, k = rem % DIM;
    if (mtx == 0)       g_Wt1[k * DIM + j] = attn_w[j * (2 * DIM) + k];
    else if (mtx == 1)  g_Wt2[k * DIM + j] = attn_w[j * (2 * DIM) + DIM + k];
    else                g_Wt3[k * DIM + j] = aggr_w[j * DIM + k];
}

__global__ void K_zeroHist(const int* __restrict__ trip) {
    int e = blockIdx.x * blockDim.x + threadIdx.x;
    if (e < NUM_REL) g_cnt[e] = 0;   // executed before any atomics below touch g_cnt? NO — same kernel.
}

// zero must complete before hist atomics: keep them as two kernels on the sort stream
__global__ void K_zero() {
    int i = blockIdx.x * blockDim.x + threadIdx.x;
    if (i < NUM_REL) g_cnt[i] = 0;
}

__global__ void K_hist(const int* __restrict__ trip) {
    int e = blockIdx.x * blockDim.x + threadIdx.x;
    if (e < NUM_EDGES) atomicAdd(&g_cnt[trip[e * 3]], 1);
}

// ---------------- 3-phase parallel scan ----------------
__global__ void K_scan1() {
    __shared__ int sh[256];
    int tid = threadIdx.x;
    int i = blockIdx.x * 256 + tid;
    int v = (i < NUM_REL) ? g_cnt[i] : 0;
    sh[tid] = v;
    __syncthreads();
#pragma unroll
    for (int off = 1; off < 256; off <<= 1) {
        int t = (tid >= off) ? sh[tid - off] : 0;
        __syncthreads();
        sh[tid] += t;
        __syncthreads();
    }
    if (i < NUM_REL) g_off[i] = sh[tid] - v;
    if (tid == 255) g_bsum[blockIdx.x] = sh[255];
}

__global__ void K_scan2() {
    __shared__ int sh[128];
    int tid = threadIdx.x;
    int v = (tid < SCAN_B) ? g_bsum[tid] : 0;
    sh[tid] = v;
    __syncthreads();
#pragma unroll
    for (int off = 1; off < 128; off <<= 1) {
        int t = (tid >= off) ? sh[tid - off] : 0;
        __syncthreads();
        sh[tid] += t;
        __syncthreads();
    }
    if (tid < SCAN_B) g_bsum[tid] = sh[tid] - v;
    if (tid == 127) g_off[NUM_REL] = sh[127];
}

__global__ void K_scan3() {
    int i = blockIdx.x * 256 + threadIdx.x;
    if (i < NUM_REL) {
        int o = g_off[i] + g_bsum[blockIdx.x];
        g_off[i] = o;
        g_cur[i] = o;
    }
}

// scatter PACKED payload: tail | bin<<20
__global__ void K_scatter(const int* __restrict__ trip) {
    int e = blockIdx.x * blockDim.x + threadIdx.x;
    if (e < NUM_EDGES) {
        int h    = trip[e * 3];
        int tail = trip[e * 3 + 1];
        int bin  = trip[e * 3 + 2];
        int pos = atomicAdd(&g_cur[h], 1);
        g_sorted[pos] = tail | (bin << 20);
    }
}

// ------- 20000x128x128 SGEMM (measured body verbatim); grid.y selects matrix -------
__global__ void K_gemm(const float* __restrict__ emb,
                       const float* __restrict__ apb,
                       const float* __restrict__ agb) {
    int which = blockIdx.y;
    const float* __restrict__ Wt = (which == 0) ? g_Wt1 : (which == 1) ? g_Wt2 : g_Wt3;
    float*       __restrict__ op = (which == 0) ? g_P1  : (which == 1) ? g_P2  : g_M;
    const float* bias = (which == 0) ? apb : (which == 1) ? (const float*)0 : agb;

    __shared__ float embS[32 * 128];
    __shared__ float WtS[32 * 132];

    int tid = threadIdx.x;
    int rbase = blockIdx.x * 32;

    const float4* eg = (const float4*)(emb + (size_t)rbase * DIM);
#pragma unroll
    for (int i = 0; i < 4; i++)
        ((float4*)embS)[tid + i * 256] = eg[tid + i * 256];

    int jt = tid & 31, j0 = jt * 4;
    int rt = tid >> 5, r0 = rt * 4;

    float acc[4][4];
#pragma unroll
    for (int a = 0; a < 4; a++)
#pragma unroll
        for (int b = 0; b < 4; b++) acc[a][b] = 0.f;

    for (int kc = 0; kc < 4; kc++) {
        __syncthreads();
#pragma unroll
        for (int i = 0; i < 4; i++) {
            int v = tid + i * 256;
            int kl = v >> 5, jq = v & 31;
            *(float4*)&WtS[kl * 132 + jq * 4] = ((const float4*)Wt)[kc * 1024 + v];
        }
        __syncthreads();
#pragma unroll
        for (int kk = 0; kk < 32; kk++) {
            int k = kc * 32 + kk;
            float4 wv = *(float4*)&WtS[kk * 132 + j0];
            float e0 = embS[(r0 + 0) * 128 + k];
            float e1 = embS[(r0 + 1) * 128 + k];
            float e2 = embS[(r0 + 2) * 128 + k];
            float e3 = embS[(r0 + 3) * 128 + k];
            acc[0][0] = fmaf(e0, wv.x, acc[0][0]); acc[0][1] = fmaf(e0, wv.y, acc[0][1]);
            acc[0][2] = fmaf(e0, wv.z, acc[0][2]); acc[0][3] = fmaf(e0, wv.w, acc[0][3]);
            acc[1][0] = fmaf(e1, wv.x, acc[1][0]); acc[1][1] = fmaf(e1, wv.y, acc[1][1]);
            acc[1][2] = fmaf(e1, wv.z, acc[1][2]); acc[1][3] = fmaf(e1, wv.w, acc[1][3]);
            acc[2][0] = fmaf(e2, wv.x, acc[2][0]); acc[2][1] = fmaf(e2, wv.y, acc[2][1]);
            acc[2][2] = fmaf(e2, wv.z, acc[2][2]); acc[2][3] = fmaf(e2, wv.w, acc[2][3]);
            acc[3][0] = fmaf(e3, wv.x, acc[3][0]); acc[3][1] = fmaf(e3, wv.y, acc[3][1]);
            acc[3][2] = fmaf(e3, wv.z, acc[3][2]); acc[3][3] = fmaf(e3, wv.w, acc[3][3]);
        }
    }

    float4 bv = make_float4(0.f, 0.f, 0.f, 0.f);
    if (bias) bv = *(const float4*)(bias + j0);
#pragma unroll
    for (int a = 0; a < 4; a++) {
        float4 o;
        o.x = acc[a][0] + bv.x; o.y = acc[a][1] + bv.y;
        o.z = acc[a][2] + bv.z; o.w = acc[a][3] + bv.w;
        *(float4*)&op[(size_t)(rbase + r0 + a) * DIM + j0] = o;
    }
}

// ------- single-pass per-relation online softmax aggregation; 4 warps -------
__global__ void K_main(const float* __restrict__ attn_bin,
                       const float* __restrict__ attn_vec,
                       float* __restrict__ out) {
    __shared__ float P1s[128];
    __shared__ float vecS[128];
    __shared__ float binS[NUM_BIN * NUM_HEAD];
    __shared__ float wM[32], wS[32], fS[32];   // [warp][head]
    __shared__ float mF[8], invS[8];
    __shared__ float accS[4 * 128];            // [warp][dim]

    int r = blockIdx.x;
    int tid = threadIdx.x;
    int start = g_off[r];
    int cnt = g_off[r + 1] - start;

    if (cnt == 0) {
        out[r * 128 + tid] = 0.f;
        return;
    }

    P1s[tid]  = g_P1[r * 128 + tid];
    vecS[tid] = attn_vec[tid];
    if (tid < NUM_BIN * NUM_HEAD) {
        float b = attn_bin[tid];
        binS[tid] = (b >= 0.f) ? b : NEG * b;
    }
    __syncthreads();

    int w = tid >> 5, lane = tid & 31, h = lane >> 2;
    float4 p1 = *(const float4*)(P1s + lane * 4);
    float4 v  = *(const float4*)(vecS + lane * 4);

    float m = -3.0e38f, s = 0.f;
    float4 acc = make_float4(0.f, 0.f, 0.f, 0.f);

#pragma unroll 2
    for (int i = w; i < cnt; i += 4) {
        int val  = g_sorted[start + i];
        int tail = val & 0xFFFFF;
        int bin  = val >> 20;
        float4 p2 = *(const float4*)(g_P2 + (size_t)tail * 128 + lane * 4);
        float4 mv = *(const float4*)(g_M  + (size_t)tail * 128 + lane * 4);
        float x0 = p1.x + p2.x; x0 = (x0 >= 0.f) ? x0 : NEG * x0;
        float x1 = p1.y + p2.y; x1 = (x1 >= 0.f) ? x1 : NEG * x1;
        float x2 = p1.z + p2.z; x2 = (x2 >= 0.f) ? x2 : NEG * x2;
        float x3 = p1.w + p2.w; x3 = (x3 >= 0.f) ? x3 : NEG * x3;
        float part = x0 * v.x + x1 * v.y + x2 * v.z + x3 * v.w;
        part += __shfl_xor_sync(0xffffffffu, part, 1);
        part += __shfl_xor_sync(0xffffffffu, part, 2);
        float score = part + binS[bin * 8 + h];
        if (score > m) {
            float c = __expf(m - score);
            s *= c;
            acc.x *= c; acc.y *= c; acc.z *= c; acc.w *= c;
            m = score;
        }
        float wt = __expf(score - m);
        s += wt;
        acc.x = fmaf(wt, mv.x, acc.x);
        acc.y = fmaf(wt, mv.y, acc.y);
        acc.z = fmaf(wt, mv.z, acc.z);
        acc.w = fmaf(wt, mv.w, acc.w);
    }

    if ((lane & 3) == 0) {
        wM[w * 8 + h] = m;
        wS[w * 8 + h] = s;
    }
    *(float4*)&accS[w * 128 + lane * 4] = acc;
    __syncthreads();

    if (tid < 8) {
        float M = -3.0e38f;
#pragma unroll
        for (int ww = 0; ww < 4; ww++) M = fmaxf(M, wM[ww * 8 + tid]);
        mF[tid] = M;
    }
    __syncthreads();
    if (tid < 32) fS[tid] = __expf(wM[tid] - mF[tid & 7]);
    __syncthreads();
    if (tid < 8) {
        float S = 0.f;
#pragma unroll
        for (int ww = 0; ww < 4; ww++) S += wS[ww * 8 + tid] * fS[ww * 8 + tid];
        invS[tid] = 1.f / (S + 1e-16f);
    }
    __syncthreads();
    {
        int hh = tid >> 4;
        float sum = 0.f;
#pragma unroll
        for (int ww = 0; ww < 4; ww++) sum += accS[ww * 128 + tid] * fS[ww * 8 + hh];
        out[r * 128 + tid] = sum * invS[hh];
    }
}

// ---------------- launch: sort chain forked onto a second stream ----------------
static cudaStream_t g_s2 = 0;
static cudaEvent_t  g_evFork = 0, g_evJoin = 0;

extern "C" void kernel_launch(void* const* d_in, const int* in_sizes, int n_in,
                              void* d_out, int out_size) {
    const float* emb  = (const float*)d_in[0];
    const int*   trip = (const int*)d_in[1];
    const float* apw  = (const float*)d_in[2];
    const float* apb  = (const float*)d_in[3];
    const float* abin = (const float*)d_in[4];
    const float* avec = (const float*)d_in[5];
    const float* agw  = (const float*)d_in[6];
    const float* agb  = (const float*)d_in[7];
    float* out = (float*)d_out;

    if (g_s2 == 0) {   // one-time host-side resource init (no device memory)
        cudaStreamCreateWithFlags(&g_s2, cudaStreamNonBlocking);
        cudaEventCreateWithFlags(&g_evFork, cudaEventDisableTiming);
        cudaEventCreateWithFlags(&g_evJoin, cudaEventDisableTiming);
    }

    // fork: sort chain on g_s2, GEMM chain on the main stream — independent until K_main
    cudaEventRecord(g_evFork, 0);
    cudaStreamWaitEvent(g_s2, g_evFork, 0);

    K_zero   <<<(NUM_REL   + 255) / 256, 256, 0, g_s2>>>();
    K_hist   <<<(NUM_EDGES + 255) / 256, 256, 0, g_s2>>>(trip);
    K_scan1  <<<SCAN_B, 256, 0, g_s2>>>();
    K_scan2  <<<1, 128, 0, g_s2>>>();
    K_scan3  <<<SCAN_B, 256, 0, g_s2>>>();
    K_scatter<<<(NUM_EDGES + 255) / 256, 256, 0, g_s2>>>(trip);
    cudaEventRecord(g_evJoin, g_s2);

    K_pre <<<(3 * DIM * DIM + 255) / 256, 256>>>(apw, agw);
    K_gemm<<<dim3(NUM_REL / 32, 3), 256>>>(emb, apb, agb);

    cudaStreamWaitEvent(0, g_evJoin, 0);   // join before the consumer
    K_main<<<NUM_REL, 128>>>(abin, avec, out);
}

// round 11
// speedup vs baseline: 2.3288x; 1.0445x over previous
#include <cuda_runtime.h>
#include <cuda_bf16.h>

#define NUM_REL   20000
#define NUM_EDGES 640000
#define DIM       128
#define NUM_HEAD  8
#define DIM_HID   16
#define NUM_BIN   10
#define NEG       0.2f
#define SCAN_B    79    // ceil(20000/256)

#define PACK2(u, lo, hi)  asm("mov.b64 %0, {%1, %2};" : "=l"(u) : "f"(lo), "f"(hi))
#define UNPACK2(lo, hi, u) asm("mov.b64 {%0, %1}, %2;" : "=f"(lo), "=f"(hi) : "l"(u))
#define FMA2(d, a, b, c)  asm("fma.rn.f32x2 %0, %1, %2, %3;" : "=l"(d) : "l"(a), "l"(b), "l"(c))

// ---------------- device scratch (static: no allocs allowed) ----------------
__device__ float g_P1[NUM_REL * DIM];
__device__ float g_P2[NUM_REL * DIM];
__device__ float g_M [NUM_REL * DIM];
__device__ float g_Wt1[DIM * DIM];
__device__ float g_Wt2[DIM * DIM];
__device__ float g_Wt3[DIM * DIM];
__device__ int   g_cnt[NUM_REL];
__device__ int   g_off[NUM_REL + 1];
__device__ int   g_cur[NUM_REL];
__device__ int   g_sorted[NUM_EDGES];   // packed: tail | (bin << 20)
__device__ int   g_bsum[SCAN_B + 1];

// ---------------- weight transpose ----------------
__global__ void K_pre(const float* __restrict__ attn_w, const float* __restrict__ aggr_w) {
    int id = blockIdx.x * blockDim.x + threadIdx.x;
    if (id >= 3 * DIM * DIM) return;
    int mtx = id / (DIM * DIM);
    int rem = id % (DIM * DIM);
    int j = rem / DIM, k = rem % DIM;
    if (mtx == 0)       g_Wt1[k * DIM + j] = attn_w[j * (2 * DIM) + k];
    else if (mtx == 1)  g_Wt2[k * DIM + j] = attn_w[j * (2 * DIM) + DIM + k];
    else                g_Wt3[k * DIM + j] = aggr_w[j * DIM + k];
}

__global__ void K_zero() {
    int i = blockIdx.x * blockDim.x + threadIdx.x;
    if (i < NUM_REL) g_cnt[i] = 0;
}

__global__ void K_hist(const int* __restrict__ trip) {
    int e = blockIdx.x * blockDim.x + threadIdx.x;
    if (e < NUM_EDGES) atomicAdd(&g_cnt[trip[e * 3]], 1);
}

// ---------------- 3-phase parallel scan ----------------
__global__ void K_scan1() {
    __shared__ int sh[256];
    int tid = threadIdx.x;
    int i = blockIdx.x * 256 + tid;
    int v = (i < NUM_REL) ? g_cnt[i] : 0;
    sh[tid] = v;
    __syncthreads();
#pragma unroll
    for (int off = 1; off < 256; off <<= 1) {
        int t = (tid >= off) ? sh[tid - off] : 0;
        __syncthreads();
        sh[tid] += t;
        __syncthreads();
    }
    if (i < NUM_REL) g_off[i] = sh[tid] - v;
    if (tid == 255) g_bsum[blockIdx.x] = sh[255];
}

__global__ void K_scan2() {
    __shared__ int sh[128];
    int tid = threadIdx.x;
    int v = (tid < SCAN_B) ? g_bsum[tid] : 0;
    sh[tid] = v;
    __syncthreads();
#pragma unroll
    for (int off = 1; off < 128; off <<= 1) {
        int t = (tid >= off) ? sh[tid - off] : 0;
        __syncthreads();
        sh[tid] += t;
        __syncthreads();
    }
    if (tid < SCAN_B) g_bsum[tid] = sh[tid] - v;
    if (tid == 127) g_off[NUM_REL] = sh[127];
}

__global__ void K_scan3() {
    int i = blockIdx.x * 256 + threadIdx.x;
    if (i < NUM_REL) {
        int o = g_off[i] + g_bsum[blockIdx.x];
        g_off[i] = o;
        g_cur[i] = o;
    }
}

__global__ void K_scatter(const int* __restrict__ trip) {
    int e = blockIdx.x * blockDim.x + threadIdx.x;
    if (e < NUM_EDGES) {
        int h    = trip[e * 3];
        int tail = trip[e * 3 + 1];
        int bin  = trip[e * 3 + 2];
        int pos = atomicAdd(&g_cur[h], 1);
        g_sorted[pos] = tail | (bin << 20);
    }
}

// ------- 20000x128x128 SGEMM, FFMA2 + transposed emb tile; grid.y selects matrix -------
#define ET_STRIDE 36   // pad: 16B-aligned float4 reads, 4-way-conflict fill (amortized)
__global__ void __launch_bounds__(256) K_gemm(const float* __restrict__ emb,
                                              const float* __restrict__ apb,
                                              const float* __restrict__ agb) {
    int which = blockIdx.y;
    const float* __restrict__ Wt = (which == 0) ? g_Wt1 : (which == 1) ? g_Wt2 : g_Wt3;
    float*       __restrict__ op = (which == 0) ? g_P1  : (which == 1) ? g_P2  : g_M;
    const float* bias = (which == 0) ? apb : (which == 1) ? (const float*)0 : agb;

    __shared__ float eT[128 * ET_STRIDE];  // [k][r], 32 rows
    __shared__ float WtS[32 * 132];        // [k_local][j] padded

    int tid = threadIdx.x;
    int rbase = blockIdx.x * 32;

    // transposed fill: coalesced LDG.32, conflict-tolerable STS.32
    for (int idx = tid; idx < 32 * 128; idx += 256) {
        int rr = idx >> 7;        // 0..31
        int kk = idx & 127;       // 0..127
        eT[kk * ET_STRIDE + rr] = emb[(size_t)(rbase + rr) * DIM + kk];
    }

    int jt = tid & 31, j0 = jt * 4;
    int rt = tid >> 5, r0 = rt * 4;

    unsigned long long acc01[4], acc23[4];
#pragma unroll
    for (int a = 0; a < 4; a++) { acc01[a] = 0ull; acc23[a] = 0ull; }

    for (int kc = 0; kc < 4; kc++) {
        __syncthreads();
#pragma unroll
        for (int i = 0; i < 4; i++) {
            int v = tid + i * 256;
            int kl = v >> 5, jq = v & 31;
            *(float4*)&WtS[kl * 132 + jq * 4] = ((const float4*)Wt)[kc * 1024 + v];
        }
        __syncthreads();
#pragma unroll
        for (int kk = 0; kk < 32; kk++) {
            int k = kc * 32 + kk;
            float4 wv = *(float4*)&WtS[kk * 132 + j0];             // LDS.128
            float4 ev = *(float4*)&eT[k * ET_STRIDE + r0];         // LDS.128 broadcast
            unsigned long long w01, w23;
            PACK2(w01, wv.x, wv.y);
            PACK2(w23, wv.z, wv.w);
            unsigned long long ee;
            PACK2(ee, ev.x, ev.x);
            FMA2(acc01[0], ee, w01, acc01[0]);
            FMA2(acc23[0], ee, w23, acc23[0]);
            PACK2(ee, ev.y, ev.y);
            FMA2(acc01[1], ee, w01, acc01[1]);
            FMA2(acc23[1], ee, w23, acc23[1]);
            PACK2(ee, ev.z, ev.z);
            FMA2(acc01[2], ee, w01, acc01[2]);
            FMA2(acc23[2], ee, w23, acc23[2]);
            PACK2(ee, ev.w, ev.w);
            FMA2(acc01[3], ee, w01, acc01[3]);
            FMA2(acc23[3], ee, w23, acc23[3]);
        }
    }

    float4 bv = make_float4(0.f, 0.f, 0.f, 0.f);
    if (bias) bv = *(const float4*)(bias + j0);
#pragma unroll
    for (int a = 0; a < 4; a++) {
        float4 o;
        UNPACK2(o.x, o.y, acc01[a]);
        UNPACK2(o.z, o.w, acc23[a]);
        o.x += bv.x; o.y += bv.y; o.z += bv.z; o.w += bv.w;
        *(float4*)&op[(size_t)(rbase + r0 + a) * DIM + j0] = o;
    }
}

// ------- single-pass per-relation online softmax aggregation; 4 warps -------
__global__ void K_main(const float* __restrict__ attn_bin,
                       const float* __restrict__ attn_vec,
                       float* __restrict__ out) {
    __shared__ float P1s[128];
    __shared__ float vecS[128];
    __shared__ float binS[NUM_BIN * NUM_HEAD];
    __shared__ float wM[32], wS[32], fS[32];   // [warp][head]
    __shared__ float mF[8], invS[8];
    __shared__ float accS[4 * 128];            // [warp][dim]

    int r = blockIdx.x;
    int tid = threadIdx.x;
    int start = g_off[r];
    int cnt = g_off[r + 1] - start;

    if (cnt == 0) {
        out[r * 128 + tid] = 0.f;
        return;
    }

    P1s[tid]  = g_P1[r * 128 + tid];
    vecS[tid] = attn_vec[tid];
    if (tid < NUM_BIN * NUM_HEAD) {
        float b = attn_bin[tid];
        binS[tid] = (b >= 0.f) ? b : NEG * b;
    }
    __syncthreads();

    int w = tid >> 5, lane = tid & 31, h = lane >> 2;
    float4 p1 = *(const float4*)(P1s + lane * 4);
    float4 v  = *(const float4*)(vecS + lane * 4);

    float m = -3.0e38f, s = 0.f;
    float4 acc = make_float4(0.f, 0.f, 0.f, 0.f);

#pragma unroll 4
    for (int i = w; i < cnt; i += 4) {
        int val  = g_sorted[start + i];
        int tail = val & 0xFFFFF;
        int bin  = val >> 20;
        float4 p2 = *(const float4*)(g_P2 + (size_t)tail * 128 + lane * 4);
        float4 mv = *(const float4*)(g_M  + (size_t)tail * 128 + lane * 4);
        float x0 = p1.x + p2.x; x0 = (x0 >= 0.f) ? x0 : NEG * x0;
        float x1 = p1.y + p2.y; x1 = (x1 >= 0.f) ? x1 : NEG * x1;
        float x2 = p1.z + p2.z; x2 = (x2 >= 0.f) ? x2 : NEG * x2;
        float x3 = p1.w + p2.w; x3 = (x3 >= 0.f) ? x3 : NEG * x3;
        float part = x0 * v.x + x1 * v.y + x2 * v.z + x3 * v.w;
        part += __shfl_xor_sync(0xffffffffu, part, 1);
        part += __shfl_xor_sync(0xffffffffu, part, 2);
        float score = part + binS[bin * 8 + h];
        if (score > m) {
            float c = __expf(m - score);
            s *= c;
            acc.x *= c; acc.y *= c; acc.z *= c; acc.w *= c;
            m = score;
        }
        float wt = __expf(score - m);
        s += wt;
        acc.x = fmaf(wt, mv.x, acc.x);
        acc.y = fmaf(wt, mv.y, acc.y);
        acc.z = fmaf(wt, mv.z, acc.z);
        acc.w = fmaf(wt, mv.w, acc.w);
    }

    if ((lane & 3) == 0) {
        wM[w * 8 + h] = m;
        wS[w * 8 + h] = s;
    }
    *(float4*)&accS[w * 128 + lane * 4] = acc;
    __syncthreads();

    if (tid < 8) {
        float M = -3.0e38f;
#pragma unroll
        for (int ww = 0; ww < 4; ww++) M = fmaxf(M, wM[ww * 8 + tid]);
        mF[tid] = M;
    }
    __syncthreads();
    if (tid < 32) fS[tid] = __expf(wM[tid] - mF[tid & 7]);
    __syncthreads();
    if (tid < 8) {
        float S = 0.f;
#pragma unroll
        for (int ww = 0; ww < 4; ww++) S += wS[ww * 8 + tid] * fS[ww * 8 + tid];
        invS[tid] = 1.f / (S + 1e-16f);
    }
    __syncthreads();
    {
        int hh = tid >> 4;
        float sum = 0.f;
#pragma unroll
        for (int ww = 0; ww < 4; ww++) sum += accS[ww * 128 + tid] * fS[ww * 8 + hh];
        out[r * 128 + tid] = sum * invS[hh];
    }
}

// ---------------- launch: sort chain forked onto a second stream ----------------
static cudaStream_t g_s2 = 0;
static cudaEvent_t  g_evFork = 0, g_evJoin = 0;

extern "C" void kernel_launch(void* const* d_in, const int* in_sizes, int n_in,
                              void* d_out, int out_size) {
    const float* emb  = (const float*)d_in[0];
    const int*   trip = (const int*)d_in[1];
    const float* apw  = (const float*)d_in[2];
    const float* apb  = (const float*)d_in[3];
    const float* abin = (const float*)d_in[4];
    const float* avec = (const float*)d_in[5];
    const float* agw  = (const float*)d_in[6];
    const float* agb  = (const float*)d_in[7];
    float* out = (float*)d_out;

    if (g_s2 == 0) {   // one-time host-side resource init (no device memory)
        cudaStreamCreateWithFlags(&g_s2, cudaStreamNonBlocking);
        cudaEventCreateWithFlags(&g_evFork, cudaEventDisableTiming);
        cudaEventCreateWithFlags(&g_evJoin, cudaEventDisableTiming);
    }

    cudaEventRecord(g_evFork, 0);
    cudaStreamWaitEvent(g_s2, g_evFork, 0);

    K_zero   <<<(NUM_REL   + 255) / 256, 256, 0, g_s2>>>();
    K_hist   <<<(NUM_EDGES + 255) / 256, 256, 0, g_s2>>>(trip);
    K_scan1  <<<SCAN_B, 256, 0, g_s2>>>();
    K_scan2  <<<1, 128, 0, g_s2>>>();
    K_scan3  <<<SCAN_B, 256, 0, g_s2>>>();
    K_scatter<<<(NUM_EDGES + 255) / 256, 256, 0, g_s2>>>(trip);
    cudaEventRecord(g_evJoin, g_s2);

    K_pre <<<(3 * DIM * DIM + 255) / 256, 256>>>(apw, agw);
    K_gemm<<<dim3(NUM_REL / 32, 3), 256>>>(emb, apb, agb);

    cudaStreamWaitEvent(0, g_evJoin, 0);
    K_main<<<NUM_REL, 128>>>(abin, avec, out);
}

// round 12
// speedup vs baseline: 2.5258x; 1.0846x over previous
#include <cuda_runtime.h>
#include <cuda_bf16.h>

#define NUM_REL   20000
#define NUM_EDGES 640000
#define DIM       128
#define NUM_HEAD  8
#define DIM_HID   16
#define NUM_BIN   10
#define NEG       0.2f
#define SCAN_B    79    // ceil(20000/256)

#define PACK2(u, lo, hi)  asm("mov.b64 %0, {%1, %2};" : "=l"(u) : "f"(lo), "f"(hi))
#define UNPACK2(lo, hi, u) asm("mov.b64 {%0, %1}, %2;" : "=f"(lo), "=f"(hi) : "l"(u))
#define FMA2(d, a, b, c)  asm("fma.rn.f32x2 %0, %1, %2, %3;" : "=l"(d) : "l"(a), "l"(b), "l"(c))

// ---------------- device scratch (static: no allocs allowed) ----------------
__device__ float g_P1[NUM_REL * DIM];
__device__ float g_P2[NUM_REL * DIM];
__device__ float g_M [NUM_REL * DIM];
__device__ float g_Wt1[DIM * DIM];
__device__ float g_Wt2[DIM * DIM];
__device__ float g_Wt3[DIM * DIM];
__device__ int   g_cnt[NUM_REL];
__device__ int   g_off[NUM_REL + 1];
__device__ int   g_cur[NUM_REL];
__device__ int   g_sorted[NUM_EDGES];   // packed: tail | (bin << 20)
__device__ int   g_bsum[SCAN_B + 1];

// ---------------- weight transpose ----------------
__global__ void K_pre(const float* __restrict__ attn_w, const float* __restrict__ aggr_w) {
    int id = blockIdx.x * blockDim.x + threadIdx.x;
    if (id >= 3 * DIM * DIM) return;
    int mtx = id / (DIM * DIM);
    int rem = id % (DIM * DIM);
    int j = rem / DIM, k = rem % DIM;
    if (mtx == 0)       g_Wt1[k * DIM + j] = attn_w[j * (2 * DIM) + k];
    else if (mtx == 1)  g_Wt2[k * DIM + j] = attn_w[j * (2 * DIM) + DIM + k];
    else                g_Wt3[k * DIM + j] = aggr_w[j * DIM + k];
}

__global__ void K_zero() {
    int i = blockIdx.x * blockDim.x + threadIdx.x;
    if (i < NUM_REL) g_cnt[i] = 0;
}

__global__ void K_hist(const int* __restrict__ trip) {
    int e = blockIdx.x * blockDim.x + threadIdx.x;
    if (e < NUM_EDGES) atomicAdd(&g_cnt[trip[e * 3]], 1);
}

// ---------------- 3-phase parallel scan ----------------
__global__ void K_scan1() {
    __shared__ int sh[256];
    int tid = threadIdx.x;
    int i = blockIdx.x * 256 + tid;
    int v = (i < NUM_REL) ? g_cnt[i] : 0;
    sh[tid] = v;
    __syncthreads();
#pragma unroll
    for (int off = 1; off < 256; off <<= 1) {
        int t = (tid >= off) ? sh[tid - off] : 0;
        __syncthreads();
        sh[tid] += t;
        __syncthreads();
    }
    if (i < NUM_REL) g_off[i] = sh[tid] - v;
    if (tid == 255) g_bsum[blockIdx.x] = sh[255];
}

__global__ void K_scan2() {
    __shared__ int sh[128];
    int tid = threadIdx.x;
    int v = (tid < SCAN_B) ? g_bsum[tid] : 0;
    sh[tid] = v;
    __syncthreads();
#pragma unroll
    for (int off = 1; off < 128; off <<= 1) {
        int t = (tid >= off) ? sh[tid - off] : 0;
        __syncthreads();
        sh[tid] += t;
        __syncthreads();
    }
    if (tid < SCAN_B) g_bsum[tid] = sh[tid] - v;
    if (tid == 127) g_off[NUM_REL] = sh[127];
}

__global__ void K_scan3() {
    int i = blockIdx.x * 256 + threadIdx.x;
    if (i < NUM_REL) {
        int o = g_off[i] + g_bsum[blockIdx.x];
        g_off[i] = o;
        g_cur[i] = o;
    }
}

__global__ void K_scatter(const int* __restrict__ trip) {
    int e = blockIdx.x * blockDim.x + threadIdx.x;
    if (e < NUM_EDGES) {
        int h    = trip[e * 3];
        int tail = trip[e * 3 + 1];
        int bin  = trip[e * 3 + 2];
        int pos = atomicAdd(&g_cur[h], 1);
        g_sorted[pos] = tail | (bin << 20);
    }
}

// ------- 20000x128x128 SGEMM, FFMA2 + transposed emb tile; grid.y selects matrix -------
#define ET_STRIDE 36
__global__ void __launch_bounds__(256) K_gemm(const float* __restrict__ emb,
                                              const float* __restrict__ apb,
                                              const float* __restrict__ agb) {
    int which = blockIdx.y;
    const float* __restrict__ Wt = (which == 0) ? g_Wt1 : (which == 1) ? g_Wt2 : g_Wt3;
    float*       __restrict__ op = (which == 0) ? g_P1  : (which == 1) ? g_P2  : g_M;
    const float* bias = (which == 0) ? apb : (which == 1) ? (const float*)0 : agb;

    __shared__ float eT[128 * ET_STRIDE];
    __shared__ float WtS[32 * 132];

    int tid = threadIdx.x;
    int rbase = blockIdx.x * 32;

    for (int idx = tid; idx < 32 * 128; idx += 256) {
        int rr = idx >> 7;
        int kk = idx & 127;
        eT[kk * ET_STRIDE + rr] = emb[(size_t)(rbase + rr) * DIM + kk];
    }

    int jt = tid & 31, j0 = jt * 4;
    int rt = tid >> 5, r0 = rt * 4;

    unsigned long long acc01[4], acc23[4];
#pragma unroll
    for (int a = 0; a < 4; a++) { acc01[a] = 0ull; acc23[a] = 0ull; }

    for (int kc = 0; kc < 4; kc++) {
        __syncthreads();
#pragma unroll
        for (int i = 0; i < 4; i++) {
            int v = tid + i * 256;
            int kl = v >> 5, jq = v & 31;
            *(float4*)&WtS[kl * 132 + jq * 4] = ((const float4*)Wt)[kc * 1024 + v];
        }
        __syncthreads();
#pragma unroll
        for (int kk = 0; kk < 32; kk++) {
            int k = kc * 32 + kk;
            float4 wv = *(float4*)&WtS[kk * 132 + j0];
            float4 ev = *(float4*)&eT[k * ET_STRIDE + r0];
            unsigned long long w01, w23;
            PACK2(w01, wv.x, wv.y);
            PACK2(w23, wv.z, wv.w);
            unsigned long long ee;
            PACK2(ee, ev.x, ev.x);
            FMA2(acc01[0], ee, w01, acc01[0]);
            FMA2(acc23[0], ee, w23, acc23[0]);
            PACK2(ee, ev.y, ev.y);
            FMA2(acc01[1], ee, w01, acc01[1]);
            FMA2(acc23[1], ee, w23, acc23[1]);
            PACK2(ee, ev.z, ev.z);
            FMA2(acc01[2], ee, w01, acc01[2]);
            FMA2(acc23[2], ee, w23, acc23[2]);
            PACK2(ee, ev.w, ev.w);
            FMA2(acc01[3], ee, w01, acc01[3]);
            FMA2(acc23[3], ee, w23, acc23[3]);
        }
    }

    float4 bv = make_float4(0.f, 0.f, 0.f, 0.f);
    if (bias) bv = *(const float4*)(bias + j0);
#pragma unroll
    for (int a = 0; a < 4; a++) {
        float4 o;
        UNPACK2(o.x, o.y, acc01[a]);
        UNPACK2(o.z, o.w, acc23[a]);
        o.x += bv.x; o.y += bv.y; o.z += bv.z; o.w += bv.w;
        *(float4*)&op[(size_t)(rbase + r0 + a) * DIM + j0] = o;
    }
}

// ------- warp-per-relation: single-pass online softmax aggregation, merge-free -------
__global__ void __launch_bounds__(256) K_main(const float* __restrict__ attn_bin,
                                              const float* __restrict__ attn_vec,
                                              float* __restrict__ out) {
    __shared__ float binS[NUM_BIN * NUM_HEAD];

    int tid = threadIdx.x;
    int w = tid >> 5, lane = tid & 31, h = lane >> 2;

    if (tid < NUM_BIN * NUM_HEAD) {
        float b = attn_bin[tid];
        binS[tid] = (b >= 0.f) ? b : NEG * b;
    }
    __syncthreads();

    int r = blockIdx.x * 8 + w;          // 2500 blocks x 8 warps = 20000 relations
    int start = g_off[r];
    int cnt = g_off[r + 1] - start;

    if (cnt == 0) {
        *(float4*)(out + (size_t)r * 128 + lane * 4) = make_float4(0.f, 0.f, 0.f, 0.f);
        return;
    }

    float4 p1 = *(const float4*)(g_P1 + (size_t)r * 128 + lane * 4);   // registers
    float4 v  = *(const float4*)(attn_vec + lane * 4);                 // L1-cached

    float m = -3.0e38f, s = 0.f;
    float4 acc = make_float4(0.f, 0.f, 0.f, 0.f);

    for (int base = 0; base < cnt; base += 32) {
        int rem = cnt - base;
        int n = (rem < 32) ? rem : 32;
        int myval = (lane < rem) ? g_sorted[start + base + lane] : 0;  // 1 coalesced LDG / 32 edges
#pragma unroll 4
        for (int i = 0; i < n; i++) {
            int val  = __shfl_sync(0xffffffffu, myval, i);             // edge data via shfl, not L2
            int tail = val & 0xFFFFF;
            int bin  = val >> 20;
            float4 p2 = *(const float4*)(g_P2 + (size_t)tail * 128 + lane * 4);
            float4 mv = *(const float4*)(g_M  + (size_t)tail * 128 + lane * 4);
            float x0 = p1.x + p2.x; x0 = (x0 >= 0.f) ? x0 : NEG * x0;
            float x1 = p1.y + p2.y; x1 = (x1 >= 0.f) ? x1 : NEG * x1;
            float x2 = p1.z + p2.z; x2 = (x2 >= 0.f) ? x2 : NEG * x2;
            float x3 = p1.w + p2.w; x3 = (x3 >= 0.f) ? x3 : NEG * x3;
            float part = x0 * v.x + x1 * v.y + x2 * v.z + x3 * v.w;
            part += __shfl_xor_sync(0xffffffffu, part, 1);
            part += __shfl_xor_sync(0xffffffffu, part, 2);   // head-group sum on all 4 lanes
            float score = part + binS[bin * 8 + h];
            if (score > m) {                                 // rare rescale
                float c = __expf(m - score);
                s *= c;
                acc.x *= c; acc.y *= c; acc.z *= c; acc.w *= c;
                m = score;
            }
            float wt = __expf(score - m);
            s += wt;
            acc.x = fmaf(wt, mv.x, acc.x);
            acc.y = fmaf(wt, mv.y, acc.y);
            acc.z = fmaf(wt, mv.z, acc.z);
            acc.w = fmaf(wt, mv.w, acc.w);
        }
    }

    float inv = 1.f / (s + 1e-16f);      // s,m replicated within head group — no merge needed
    float4 o;
    o.x = acc.x * inv; o.y = acc.y * inv; o.z = acc.z * inv; o.w = acc.w * inv;
    *(float4*)(out + (size_t)r * 128 + lane * 4) = o;
}

// ---------------- launch: sort chain forked onto a second stream ----------------
static cudaStream_t g_s2 = 0;
static cudaEvent_t  g_evFork = 0, g_evJoin = 0;

extern "C" void kernel_launch(void* const* d_in, const int* in_sizes, int n_in,
                              void* d_out, int out_size) {
    const float* emb  = (const float*)d_in[0];
    const int*   trip = (const int*)d_in[1];
    const float* apw  = (const float*)d_in[2];
    const float* apb  = (const float*)d_in[3];
    const float* abin = (const float*)d_in[4];
    const float* avec = (const float*)d_in[5];
    const float* agw  = (const float*)d_in[6];
    const float* agb  = (const float*)d_in[7];
    float* out = (float*)d_out;

    if (g_s2 == 0) {
        cudaStreamCreateWithFlags(&g_s2, cudaStreamNonBlocking);
        cudaEventCreateWithFlags(&g_evFork, cudaEventDisableTiming);
        cudaEventCreateWithFlags(&g_evJoin, cudaEventDisableTiming);
    }

    cudaEventRecord(g_evFork, 0);
    cudaStreamWaitEvent(g_s2, g_evFork, 0);

    K_zero   <<<(NUM_REL   + 255) / 256, 256, 0, g_s2>>>();
    K_hist   <<<(NUM_EDGES + 255) / 256, 256, 0, g_s2>>>(trip);
    K_scan1  <<<SCAN_B, 256, 0, g_s2>>>();
    K_scan2  <<<1, 128, 0, g_s2>>>();
    K_scan3  <<<SCAN_B, 256, 0, g_s2>>>();
    K_scatter<<<(NUM_EDGES + 255) / 256, 256, 0, g_s2>>>(trip);
    cudaEventRecord(g_evJoin, g_s2);

    K_pre <<<(3 * DIM * DIM + 255) / 256, 256>>>(apw, agw);
    K_gemm<<<dim3(NUM_REL / 32, 3), 256>>>(emb, apb, agb);

    cudaStreamWaitEvent(0, g_evJoin, 0);
    K_main<<<NUM_REL / 8, 256>>>(abin, avec, out);
}